// round 1
// baseline (speedup 1.0000x reference)
#include <cuda_runtime.h>
#include <stdint.h>

#define BOX 120
#define BOX2 (BOX * BOX)
#define BOX3 (BOX * BOX * BOX)
#define MAX_ATOMS_C 512
#define BT_C 44            // BATCH(4) * NUM_TYPES(11)
#define PAIRS 25           // 5x5 (ox,oy) offsets

// ---------------------------------------------------------------------------
// Kernel 1: zero the output volume. Pure STG.128 stream — HBM-bound.
// ---------------------------------------------------------------------------
__global__ void zero_vec4_kernel(float4* __restrict__ out, long long n4) {
    long long i = (long long)blockIdx.x * blockDim.x + threadIdx.x;
    if (i < n4) out[i] = make_float4(0.f, 0.f, 0.f, 0.f);
}

__global__ void zero_scalar_kernel(float* __restrict__ out, long long n) {
    long long i = (long long)blockIdx.x * blockDim.x + threadIdx.x;
    if (i < n) out[i] = 0.f;
}

// ---------------------------------------------------------------------------
// Kernel 2: scatter truncated Gaussians.
// One thread per (bt, atom, (ox,oy)) pair; inner loop over 5 z cells
// (contiguous addresses). Separable weight: exp(-(dx^2+dy^2)) * exp(-dz^2).
// atomicAdd with unused return compiles to REDG (no round trip).
// ---------------------------------------------------------------------------
__global__ void scatter_kernel(const float* __restrict__ coords,
                               const void* __restrict__ natoms_raw,
                               float* __restrict__ out) {
    int tid = blockIdx.x * blockDim.x + threadIdx.x;
    int pair = tid % PAIRS;
    int rest = tid / PAIRS;
    if (rest >= BT_C * MAX_ATOMS_C) return;
    int a  = rest % MAX_ATOMS_C;
    int bt = rest / MAX_ATOMS_C;

    // num_atoms may arrive as int64 or int32 (jax x64 flag). Probe element 0:
    // if the buffer is int32-packed, the int64 view of element 0 contains
    // n[1] (>=1) in its high word -> value >= 2^32, outside [1, 512].
    const long long* n64 = (const long long*)natoms_raw;
    const int*       n32 = (const int*)natoms_raw;
    long long probe = n64[0];
    bool is64 = (probe >= 1 && probe <= MAX_ATOMS_C);
    int n = is64 ? (int)n64[bt] : n32[bt];
    if (a >= n) return;

    const float* c = coords + (long long)bt * (3 * MAX_ATOMS_C) + 3 * a;
    float x = c[0], y = c[1], z = c[2];
    int cx = (int)floorf(x);
    int cy = (int)floorf(y);
    int cz = (int)floorf(z);

    int ox = pair / 5 - 2;
    int oy = pair % 5 - 2;
    int gx = cx + ox;
    int gy = cy + oy;
    if ((unsigned)gx >= BOX || (unsigned)gy >= BOX) return;

    float dx = (float)gx - x;
    float dy = (float)gy - y;
    float wxy = __expf(-(dx * dx + dy * dy));

    float* base = out + (long long)bt * BOX3 + ((long long)gx * BOX + gy) * BOX;

    #pragma unroll
    for (int oz = -2; oz <= 2; ++oz) {
        int gz = cz + oz;
        if ((unsigned)gz < BOX) {
            float dz = (float)gz - z;
            atomicAdd(base + gz, wxy * __expf(-dz * dz));
        }
    }
}

// ---------------------------------------------------------------------------
// Launch
// ---------------------------------------------------------------------------
extern "C" void kernel_launch(void* const* d_in, const int* in_sizes, int n_in,
                              void* d_out, int out_size) {
    const float* coords = (const float*)d_in[0];
    const void*  natoms = d_in[1];
    float* out = (float*)d_out;

    // 1) zero the volume
    long long n = (long long)out_size;
    if ((n & 3LL) == 0) {
        long long n4 = n >> 2;
        int threads = 256;
        long long blocks = (n4 + threads - 1) / threads;
        zero_vec4_kernel<<<(unsigned)blocks, threads>>>((float4*)out, n4);
    } else {
        int threads = 256;
        long long blocks = (n + threads - 1) / threads;
        zero_scalar_kernel<<<(unsigned)blocks, threads>>>(out, n);
    }

    // 2) scatter gaussians
    {
        int total = BT_C * MAX_ATOMS_C * PAIRS;  // 563,200
        int threads = 256;
        int blocks = (total + threads - 1) / threads;
        scatter_kernel<<<blocks, threads>>>(coords, natoms, out);
    }
}